// round 11
// baseline (speedup 1.0000x reference)
#include <cuda_runtime.h>
#include <cuda_bf16.h>
#include <cstdint>

#define SEQ   2048
#define D_IN  300
#define U     150
#define NZ    600      // 4 gates * U
#define H1    300
#define TE    8        // timestep tile for embZ
#define TT    4        // timestep tile for outGemm
#define NCTA  8        // cluster size; 8 = portable max
#define SLICE 20       // h-outputs owned per CTA rank (rank7: 10 real + 10 pad)
#define KP    160      // padded recurrence depth = NCTA*SLICE
#define KH    80       // split-k half depth
#define W2N   40       // f32x2 weights per thread per direction (KH/2)
#define OFFB  (2 * KP * 4)   // byte offset dirA -> dirB inside h_sh
#define BOFFB 16             // byte offset dirA -> dirB inside mbar_sh

// ------------------------- scratch (static device memory; no allocs) ---------
__device__ float g_Z[2][SEQ][NZ];        // precomputed x@Wk + b, per direction
__device__ float g_hidden[SEQ][H1];      // [hf | hb] concat
__device__ float g_out[SEQ][H1];         // hidden @ W1 + b1
__device__ float g_H[H1];                // final weighted sum

// ------------------------- small PTX helpers ---------------------------------
__device__ __forceinline__ uint32_t smem_u32(const void* p) {
    return (uint32_t)__cvta_generic_to_shared(p);
}
__device__ __forceinline__ uint32_t mapa_rank(uint32_t addr, uint32_t r) {
    uint32_t out;
    asm("mapa.shared::cluster.u32 %0, %1, %2;" : "=r"(out) : "r"(addr), "r"(r));
    return out;
}
__device__ __forceinline__ void cluster_sync_() {
    asm volatile("barrier.cluster.arrive.aligned;" ::: "memory");
    asm volatile("barrier.cluster.wait.aligned;" ::: "memory");
}
__device__ __forceinline__ uint32_t my_cluster_rank() {
    uint32_t r;
    asm("mov.u32 %0, %%cluster_ctarank;" : "=r"(r));
    return r;
}
__device__ __forceinline__ unsigned long long pack2(float lo, float hi) {
    unsigned long long r;
    asm("mov.b64 %0, {%1, %2};" : "=l"(r) : "f"(lo), "f"(hi));
    return r;
}
__device__ __forceinline__ void fma2(unsigned long long& d, unsigned long long a,
                                     unsigned long long b) {
    asm("fma.rn.f32x2 %0, %1, %2, %0;" : "+l"(d) : "l"(a), "l"(b));
}
__device__ __forceinline__ void unpack2(unsigned long long v, float& lo, float& hi) {
    asm("mov.b64 {%0, %1}, %2;" : "=f"(lo), "=f"(hi) : "l"(v));
}
__device__ __forceinline__ float tanh_approx(float x) {
    float r;
    asm("tanh.approx.f32 %0, %1;" : "=f"(r) : "f"(x));
    return r;
}
__device__ __forceinline__ void mbar_init(uint32_t addr, uint32_t cnt) {
    asm volatile("mbarrier.init.shared.b64 [%0], %1;" :: "r"(addr), "r"(cnt) : "memory");
}
__device__ __forceinline__ void mbar_arrive_expect_tx(uint32_t addr, uint32_t tx) {
    asm volatile("mbarrier.arrive.expect_tx.shared.b64 _, [%0], %1;"
                 :: "r"(addr), "r"(tx) : "memory");
}
// CTA-scope acquire wait — st.async completion (complete_tx) provides the
// cross-CTA visibility; no cluster-scope fence -> no per-step L1D flush.
__device__ __forceinline__ void mbar_wait_parity_cta(uint32_t addr, uint32_t parity) {
    asm volatile(
        "{\n\t"
        ".reg .pred P1;\n\t"
        "WAIT_LOOP_%=:\n\t"
        "mbarrier.try_wait.parity.acquire.cta.shared::cta.b64 P1, [%0], %1, 0x989680;\n\t"
        "@P1 bra.uni WAIT_DONE_%=;\n\t"
        "bra.uni WAIT_LOOP_%=;\n\t"
        "WAIT_DONE_%=:\n\t"
        "}"
        :: "r"(addr), "r"(parity) : "memory");
}
// one 16-byte vector store, ONE complete_tx transaction at the target barrier
__device__ __forceinline__ void st_async_v4(uint32_t daddr, float x, float y,
                                            float z, float w, uint32_t mbar) {
    asm volatile(
        "st.async.shared::cluster.mbarrier::complete_tx::bytes.v4.b32 "
        "[%0], {%1, %2, %3, %4}, [%5];"
        :: "r"(daddr), "f"(x), "f"(y), "f"(z), "f"(w), "r"(mbar) : "memory");
}

// ============================================================================
// Kernel 0: zero the accumulator for H
// ============================================================================
__global__ void zeroH_kernel() {
    if (threadIdx.x < H1) g_H[threadIdx.x] = 0.f;
}

// ============================================================================
// Kernel 1: Z[dir][t][:] = x_t @ Wk + b, tiled over TE=8 timesteps.
// grid (SEQ/TE, 2), block 160.
// ============================================================================
__global__ void __launch_bounds__(160) embZ_kernel(
    const int* __restrict__ sentence, const float* __restrict__ E,
    const float* __restrict__ Wk_f, const float* __restrict__ b_f,
    const float* __restrict__ Wk_b, const float* __restrict__ b_b)
{
    __shared__ float x_sh[TE][D_IN];
    const int t0  = blockIdx.x * TE;
    const int dir = blockIdx.y;

    for (int i = threadIdx.x; i < TE * D_IN; i += 160) {
        const int r = i / D_IN, d = i % D_IN;
        x_sh[r][d] = E[(size_t)sentence[t0 + r] * D_IN + d];
    }
    __syncthreads();

    const float* __restrict__ Wk = dir ? Wk_b : Wk_f;
    const float* __restrict__ b  = dir ? b_b  : b_f;

    const int j = threadIdx.x * 4;
    if (j < NZ) {
        const float4 bv = *(const float4*)(b + j);
        float4 acc[TE];
        #pragma unroll
        for (int r = 0; r < TE; r++) acc[r] = bv;

        #pragma unroll 2
        for (int d = 0; d < D_IN; d++) {
            const float4 wv = *(const float4*)(Wk + d * NZ + j);
            #pragma unroll
            for (int r = 0; r < TE; r++) {
                const float x = x_sh[r][d];
                acc[r].x = fmaf(x, wv.x, acc[r].x);
                acc[r].y = fmaf(x, wv.y, acc[r].y);
                acc[r].z = fmaf(x, wv.z, acc[r].z);
                acc[r].w = fmaf(x, wv.w, acc[r].w);
            }
        }
        #pragma unroll
        for (int r = 0; r < TE; r++)
            *(float4*)&g_Z[dir][t0 + r][j] = acc[r];
    }
}

// ============================================================================
// Kernel 2: bidirectional LSTM recurrence — BOTH DIRECTIONS INTERLEAVED in
// ONE 8-CTA cluster, output-sliced, sync-free inner loop.
// grid (8,1), cluster (8,1,1). CTA rank r owns h-outputs [r*20, r*20+20)
// (rank7: 10 real + 10 pad) for all 4 gates, for BOTH directions (weights
// for both register-resident). Per iteration: waitA/dotA/pushA then
// waitB/dotB/pushB — each direction's DSMEM transit + barrier-tx accumulation
// is hidden behind the other direction's compute, so the waits hit the
// already-complete fast path. Gate exchange via intra-warp shfl; h delivered
// to all 8 CTAs (incl. self) via st.async.v4 + double-buffered mbarriers.
// dirB smem addresses = dirA + compile-time offsets (mapa is linear).
// ============================================================================
__global__ void __cluster_dims__(NCTA, 1, 1) __launch_bounds__(160, 1)
lstm_rec_kernel(const float* __restrict__ Wr_f, const float* __restrict__ Wr_b)
{
    __shared__ __align__(16) float h_sh[2][2][KP];  // [dir][buf][KP]
    __shared__ __align__(8)  unsigned long long mbar_sh[2][2];  // [dir][buf]

    const int tid  = threadIdx.x;
    const int wrp  = tid >> 5;
    const int lane = tid & 31;
    const int u    = tid >> 1;         // unit 0..79
    const int kh   = tid & 1;          // k-half: 0 -> k[0..79], 1 -> k[80..159]
    const int g    = u & 3;            // gate 0=i 1=f 2=g 3=o
    const int o    = u >> 2;           // local output 0..19
    const uint32_t rank = my_cluster_rank();
    const int obase = rank * SLICE;
    const int myo   = obase + o;       // global output index
    const bool unit_act = (myo < U);
    const bool lead  = unit_act && (kh == 0);
    const bool cellT = lead && (g == 0);
    const int col = unit_act ? (g * U + myo) : 0;
    const uint32_t inbytes = KP * 4;   // 640B: all 8 ranks incl. self

    if (tid < KP) {
        h_sh[0][0][tid] = 0.f; h_sh[0][1][tid] = 0.f;
        h_sh[1][0][tid] = 0.f; h_sh[1][1][tid] = 0.f;
    }
    if (tid == 0) {
        mbar_init(smem_u32(&mbar_sh[0][0]), 1);
        mbar_init(smem_u32(&mbar_sh[0][1]), 1);
        mbar_init(smem_u32(&mbar_sh[1][0]), 1);
        mbar_init(smem_u32(&mbar_sh[1][1]), 1);
    }

    // register-resident weights for BOTH directions (my k-half of column col)
    unsigned long long w2A[W2N], w2B[W2N];
    #pragma unroll
    for (int jj = 0; jj < W2N; jj++) {
        const int k = kh * KH + 2 * jj;
        float wa = 0.f, wb = 0.f, wc = 0.f, wd = 0.f;
        if (unit_act && k     < U) { wa = Wr_f[k * NZ + col];       wc = Wr_b[k * NZ + col]; }
        if (unit_act && k + 1 < U) { wb = Wr_f[(k + 1) * NZ + col]; wd = Wr_b[(k + 1) * NZ + col]; }
        w2A[jj] = pack2(wa, wb);
        w2B[jj] = pack2(wc, wd);
    }

    // push targets for dirA (dirB = +OFFB / +BOFFB, mapa is offset-linear).
    // lane0 covers ranks 0-3, lane16 covers ranks 4-7.
    const uint32_t rbase = (lane >= 16) ? 4u : 0u;
    uint32_t pdst[2][4], pbar[2][4];
    {
        const uint32_t l0 = smem_u32(&h_sh[0][0][obase + 4 * wrp]);
        const uint32_t l1 = smem_u32(&h_sh[0][1][obase + 4 * wrp]);
        const uint32_t b0 = smem_u32(&mbar_sh[0][0]);
        const uint32_t b1 = smem_u32(&mbar_sh[0][1]);
        #pragma unroll
        for (uint32_t i = 0; i < 4; i++) {
            pdst[0][i] = mapa_rank(l0, rbase + i);
            pdst[1][i] = mapa_rank(l1, rbase + i);
            pbar[0][i] = mapa_rank(b0, rbase + i);
            pbar[1][i] = mapa_rank(b1, rbase + i);
        }
    }
    const uint32_t my_barA[2] = { smem_u32(&mbar_sh[0][0]), smem_u32(&mbar_sh[0][1]) };
    const uint32_t my_barB[2] = { smem_u32(&mbar_sh[1][0]), smem_u32(&mbar_sh[1][1]) };

    float cA = 0.f, cB = 0.f;      // cell states (cell threads only)
    int parA[2] = { 0, 0 }, parB[2] = { 0, 0 };
    __syncthreads();
    cluster_sync_();               // barriers + zeroed h live cluster-wide

    float zpreA = lead ? __ldg(&g_Z[0][0][col]) : 0.f;
    float zpreB = lead ? __ldg(&g_Z[1][SEQ - 1][col]) : 0.f;
    const int lbase = lane & 24;   // base lane of my 8-lane output group
    const unsigned m = 0xffffffffu;

    for (int ti = 0; ti < SEQ; ti++) {
        const int b  = ti & 1;
        const int nb = b ^ 1;
        const bool more = (ti + 1 < SEQ);

        // ===================== direction A (forward) =====================
        if (ti > 0) { mbar_wait_parity_cta(my_barA[b], parA[b]); parA[b] ^= 1; }
        if (tid == 0 && more) mbar_arrive_expect_tx(my_barA[nb], inbytes);

        float znA = 0.f;
        if (lead && more) znA = __ldg(&g_Z[0][ti + 1][col]);

        {
            unsigned long long a0 = pack2(zpreA, 0.f), a1 = pack2(0.f, 0.f);
            const ulonglong2* hp = (const ulonglong2*)&h_sh[0][b][kh * KH];
            #pragma unroll
            for (int j = 0; j < W2N / 2; j++) {
                const ulonglong2 hv = hp[j];
                fma2(a0, hv.x, w2A[2 * j + 0]);
                fma2(a1, hv.y, w2A[2 * j + 1]);
            }
            float f0, f1, f2, f3;
            unpack2(a0, f0, f1);
            unpack2(a1, f2, f3);
            float z = (f0 + f2) + (f1 + f3);
            z += __shfl_xor_sync(m, z, 1);

            // single-MUFU activation: sigmoid(x) = 0.5*tanh(0.5x)+0.5
            const float targ = (g == 2) ? z : 0.5f * z;
            const float tv   = tanh_approx(targ);
            const float a    = (g == 2) ? tv : fmaf(0.5f, tv, 0.5f);

            const float af = __shfl_sync(m, a, lbase + 2);
            const float ag = __shfl_sync(m, a, lbase + 4);
            const float ao = __shfl_sync(m, a, lbase + 6);

            float hval = 0.f;
            if (cellT) {
                cA = fmaf(af, cA, a * ag);
                hval = ao * tanh_approx(cA);
            }
            if (more) {
                const float vx = __shfl_sync(m, hval, 0);
                const float vy = __shfl_sync(m, hval, 8);
                const float vz = __shfl_sync(m, hval, 16);
                const float vw = __shfl_sync(m, hval, 24);
                if ((lane & 15) == 0) {
                    st_async_v4(pdst[nb][0], vx, vy, vz, vw, pbar[nb][0]);
                    st_async_v4(pdst[nb][1], vx, vy, vz, vw, pbar[nb][1]);
                    st_async_v4(pdst[nb][2], vx, vy, vz, vw, pbar[nb][2]);
                    st_async_v4(pdst[nb][3], vx, vy, vz, vw, pbar[nb][3]);
                }
            }
            if (cellT) g_hidden[ti][myo] = hval;
        }
        zpreA = znA;

        // ===================== direction B (backward) ====================
        if (ti > 0) { mbar_wait_parity_cta(my_barB[b], parB[b]); parB[b] ^= 1; }
        if (tid == 0 && more) mbar_arrive_expect_tx(my_barB[nb], inbytes);

        float znB = 0.f;
        if (lead && more) znB = __ldg(&g_Z[1][SEQ - 2 - ti][col]);

        {
            unsigned long long a0 = pack2(zpreB, 0.f), a1 = pack2(0.f, 0.f);
            const ulonglong2* hp = (const ulonglong2*)&h_sh[1][b][kh * KH];
            #pragma unroll
            for (int j = 0; j < W2N / 2; j++) {
                const ulonglong2 hv = hp[j];
                fma2(a0, hv.x, w2B[2 * j + 0]);
                fma2(a1, hv.y, w2B[2 * j + 1]);
            }
            float f0, f1, f2, f3;
            unpack2(a0, f0, f1);
            unpack2(a1, f2, f3);
            float z = (f0 + f2) + (f1 + f3);
            z += __shfl_xor_sync(m, z, 1);

            const float targ = (g == 2) ? z : 0.5f * z;
            const float tv   = tanh_approx(targ);
            const float a    = (g == 2) ? tv : fmaf(0.5f, tv, 0.5f);

            const float af = __shfl_sync(m, a, lbase + 2);
            const float ag = __shfl_sync(m, a, lbase + 4);
            const float ao = __shfl_sync(m, a, lbase + 6);

            float hval = 0.f;
            if (cellT) {
                cB = fmaf(af, cB, a * ag);
                hval = ao * tanh_approx(cB);
            }
            if (more) {
                const float vx = __shfl_sync(m, hval, 0);
                const float vy = __shfl_sync(m, hval, 8);
                const float vz = __shfl_sync(m, hval, 16);
                const float vw = __shfl_sync(m, hval, 24);
                if ((lane & 15) == 0) {
                    st_async_v4(pdst[nb][0] + OFFB, vx, vy, vz, vw, pbar[nb][0] + BOFFB);
                    st_async_v4(pdst[nb][1] + OFFB, vx, vy, vz, vw, pbar[nb][1] + BOFFB);
                    st_async_v4(pdst[nb][2] + OFFB, vx, vy, vz, vw, pbar[nb][2] + BOFFB);
                    st_async_v4(pdst[nb][3] + OFFB, vx, vy, vz, vw, pbar[nb][3] + BOFFB);
                }
            }
            if (cellT) g_hidden[SEQ - 1 - ti][U + myo] = hval;
        }
        zpreB = znB;
    }
    cluster_sync_();               // keep peers alive until traffic retired
}

// ============================================================================
// Kernel 3: out = hidden @ W1 + b1, TT=4 rows per block (measured best).
// ============================================================================
__global__ void __launch_bounds__(320) outGemm_kernel(
    const float* __restrict__ W1, const float* __restrict__ b1)
{
    __shared__ float hrow[TT][H1];
    const int t0 = blockIdx.x * TT;
    for (int i = threadIdx.x; i < TT * H1; i += 320)
        hrow[i / H1][i % H1] = g_hidden[t0 + i / H1][i % H1];
    __syncthreads();

    const int j = threadIdx.x;
    if (j < H1) {
        const float bj = b1[j];
        float acc[TT];
        #pragma unroll
        for (int r = 0; r < TT; r++) acc[r] = bj;
        #pragma unroll 4
        for (int d = 0; d < H1; d++) {
            const float w = __ldg(&W1[d * H1 + j]);
            #pragma unroll
            for (int r = 0; r < TT; r++) acc[r] = fmaf(hrow[r][d], w, acc[r]);
        }
        #pragma unroll
        for (int r = 0; r < TT; r++) g_out[t0 + r][j] = acc[r];
    }
}

// ============================================================================
// Kernel 4: per-position synonym attention + h_hat + c2, accumulate H.
// grid SEQ, block 128 (warp k handles synonym k).
// ============================================================================
__global__ void __launch_bounds__(128) syn_kernel(
    const int* __restrict__ sentence, const int* __restrict__ syn,
    const float* __restrict__ E,
    const float* __restrict__ W2, const float* __restrict__ b2)
{
    __shared__ float orow[H1];
    __shared__ float hhat[H1];
    __shared__ float e_sh[4][H1];
    __shared__ float coeff_sh[4];
    __shared__ float red_sh[4];
    __shared__ float c2_sh;

    const int s    = blockIdx.x;
    const int idx  = s ? (s - 1) : 0;
    const int tid  = threadIdx.x;
    const int wid  = tid >> 5;
    const int lane = tid & 31;

    for (int d = tid; d < H1; d += 128) {
        orow[d] = g_out[idx][d];
        hhat[d] = g_hidden[idx][d];
    }
    __syncthreads();

    {
        const int tok = sentence[s];
        const float* __restrict__ e = E + (size_t)syn[tok * 4 + wid] * D_IN;
        float p = 0.f;
        for (int d = lane; d < H1; d += 32) {
            const float ev = e[d];
            e_sh[wid][d] = ev;
            p = fmaf(ev, orow[d], p);
        }
        #pragma unroll
        for (int o = 16; o > 0; o >>= 1) p += __shfl_xor_sync(0xffffffffu, p, o);
        if (lane == 0) coeff_sh[wid] = __expf(p);
    }
    __syncthreads();

    const float c0 = coeff_sh[0], c1 = coeff_sh[1], c2c = coeff_sh[2], c3 = coeff_sh[3];
    for (int d = tid; d < H1; d += 128) {
        float v = hhat[d];
        v = fmaf(c0, e_sh[0][d], v);
        v = fmaf(c1, e_sh[1][d], v);
        v = fmaf(c2c, e_sh[2][d], v);
        v = fmaf(c3, e_sh[3][d], v);
        hhat[d] = v;
    }
    __syncthreads();

    float p = 0.f;
    for (int d = tid; d < H1; d += 128) p = fmaf(hhat[d], W2[d], p);
    #pragma unroll
    for (int o = 16; o > 0; o >>= 1) p += __shfl_xor_sync(0xffffffffu, p, o);
    if (lane == 0) red_sh[wid] = p;
    __syncthreads();
    if (tid == 0)
        c2_sh = __expf(tanhf(red_sh[0] + red_sh[1] + red_sh[2] + red_sh[3] + b2[0]));
    __syncthreads();

    const float c2 = c2_sh;
    for (int d = tid; d < H1; d += 128) atomicAdd(&g_H[d], c2 * hhat[d]);
}

// ============================================================================
// Kernel 5: heads — out[0..7] = H@We + be, out[8] = H@Ws + bs
// ============================================================================
__global__ void heads_kernel(
    const float* __restrict__ We, const float* __restrict__ be,
    const float* __restrict__ Ws, const float* __restrict__ bs,
    float* __restrict__ out)
{
    const int j = threadIdx.x;
    if (j < 8) {
        float acc = be[j];
        for (int d = 0; d < H1; d++) acc = fmaf(g_H[d], We[d * 8 + j], acc);
        out[j] = acc;
    } else if (j == 8) {
        float acc = bs[0];
        for (int d = 0; d < H1; d++) acc = fmaf(g_H[d], Ws[d], acc);
        out[8] = acc;
    }
}

// ============================================================================
extern "C" void kernel_launch(void* const* d_in, const int* in_sizes, int n_in,
                              void* d_out, int out_size)
{
    const int*   sentence = (const int*)  d_in[0];
    const int*   syn      = (const int*)  d_in[1];
    const float* E        = (const float*)d_in[2];
    const float* Wk_f     = (const float*)d_in[3];
    const float* Wr_f     = (const float*)d_in[4];
    const float* b_f      = (const float*)d_in[5];
    const float* Wk_b     = (const float*)d_in[6];
    const float* Wr_b     = (const float*)d_in[7];
    const float* b_b      = (const float*)d_in[8];
    const float* W1       = (const float*)d_in[9];
    const float* b1       = (const float*)d_in[10];
    const float* W2       = (const float*)d_in[11];
    const float* b2       = (const float*)d_in[12];
    const float* We       = (const float*)d_in[13];
    const float* be       = (const float*)d_in[14];
    const float* Ws       = (const float*)d_in[15];
    const float* bs       = (const float*)d_in[16];
    float* out = (float*)d_out;

    zeroH_kernel<<<1, 320>>>();
    embZ_kernel<<<dim3(SEQ / TE, 2), 160>>>(sentence, E, Wk_f, b_f, Wk_b, b_b);
    lstm_rec_kernel<<<dim3(NCTA, 1), 160>>>(Wr_f, Wr_b);
    outGemm_kernel<<<SEQ / TT, 320>>>(W1, b1);
    syn_kernel<<<SEQ, 128>>>(sentence, syn, E, W2, b2);
    heads_kernel<<<1, 32>>>(We, be, Ws, bs, out);
}

// round 12
// speedup vs baseline: 1.4672x; 1.4672x over previous
#include <cuda_runtime.h>
#include <cuda_bf16.h>
#include <cstdint>

#define SEQ   2048
#define D_IN  300
#define U     150
#define NZ    600      // 4 gates * U
#define H1    300
#define TE    8        // timestep tile for embZ
#define TT    4        // timestep tile for outGemm (measured best)
#define NCTA  8        // cluster size (CTAs per direction); 8 = portable max
#define SLICE 20       // h-outputs owned per CTA rank (rank7: 10 real + 10 pad)
#define KP    160      // padded recurrence depth = NCTA*SLICE
#define KH    80       // split-k half depth
#define W2N   40       // f32x2 weights per thread (KH/2)

// ------------------------- scratch (static device memory; no allocs) ---------
__device__ float g_Z[2][SEQ][NZ];        // precomputed x@Wk + b, per direction
__device__ float g_hidden[SEQ][H1];      // [hf | hb] concat
__device__ float g_out[SEQ][H1];         // hidden @ W1 + b1
__device__ float g_H[H1];                // final weighted sum

// ------------------------- small PTX helpers ---------------------------------
__device__ __forceinline__ uint32_t smem_u32(const void* p) {
    return (uint32_t)__cvta_generic_to_shared(p);
}
__device__ __forceinline__ uint32_t mapa_rank(uint32_t addr, uint32_t r) {
    uint32_t out;
    asm("mapa.shared::cluster.u32 %0, %1, %2;" : "=r"(out) : "r"(addr), "r"(r));
    return out;
}
__device__ __forceinline__ void cluster_sync_() {
    asm volatile("barrier.cluster.arrive.aligned;" ::: "memory");
    asm volatile("barrier.cluster.wait.aligned;" ::: "memory");
}
__device__ __forceinline__ uint32_t my_cluster_rank() {
    uint32_t r;
    asm("mov.u32 %0, %%cluster_ctarank;" : "=r"(r));
    return r;
}
__device__ __forceinline__ unsigned long long pack2(float lo, float hi) {
    unsigned long long r;
    asm("mov.b64 %0, {%1, %2};" : "=l"(r) : "f"(lo), "f"(hi));
    return r;
}
__device__ __forceinline__ void fma2(unsigned long long& d, unsigned long long a,
                                     unsigned long long b) {
    asm("fma.rn.f32x2 %0, %1, %2, %0;" : "+l"(d) : "l"(a), "l"(b));
}
__device__ __forceinline__ void unpack2(unsigned long long v, float& lo, float& hi) {
    asm("mov.b64 {%0, %1}, %2;" : "=f"(lo), "=f"(hi) : "l"(v));
}
__device__ __forceinline__ float tanh_approx(float x) {
    float r;
    asm("tanh.approx.f32 %0, %1;" : "=f"(r) : "f"(x));
    return r;
}
__device__ __forceinline__ void mbar_init(uint32_t addr, uint32_t cnt) {
    asm volatile("mbarrier.init.shared.b64 [%0], %1;" :: "r"(addr), "r"(cnt) : "memory");
}
__device__ __forceinline__ void mbar_arrive_expect_tx(uint32_t addr, uint32_t tx) {
    asm volatile("mbarrier.arrive.expect_tx.shared.b64 _, [%0], %1;"
                 :: "r"(addr), "r"(tx) : "memory");
}
// CTA-scope acquire wait — st.async completion (complete_tx) provides the
// cross-CTA visibility; no cluster-scope fence -> no per-step L1D flush.
__device__ __forceinline__ void mbar_wait_parity_cta(uint32_t addr, uint32_t parity) {
    asm volatile(
        "{\n\t"
        ".reg .pred P1;\n\t"
        "WAIT_LOOP_%=:\n\t"
        "mbarrier.try_wait.parity.acquire.cta.shared::cta.b64 P1, [%0], %1, 0x989680;\n\t"
        "@P1 bra.uni WAIT_DONE_%=;\n\t"
        "bra.uni WAIT_LOOP_%=;\n\t"
        "WAIT_DONE_%=:\n\t"
        "}"
        :: "r"(addr), "r"(parity) : "memory");
}
// one 16-byte vector store, ONE complete_tx transaction at the target barrier
__device__ __forceinline__ void st_async_v4(uint32_t daddr, float x, float y,
                                            float z, float w, uint32_t mbar) {
    asm volatile(
        "st.async.shared::cluster.mbarrier::complete_tx::bytes.v4.b32 "
        "[%0], {%1, %2, %3, %4}, [%5];"
        :: "r"(daddr), "f"(x), "f"(y), "f"(z), "f"(w), "r"(mbar) : "memory");
}

// ============================================================================
// Kernel 0: zero the accumulator for H
// ============================================================================
__global__ void zeroH_kernel() {
    if (threadIdx.x < H1) g_H[threadIdx.x] = 0.f;
}

// ============================================================================
// Kernel 1: Z[dir][t][:] = x_t @ Wk + b, tiled over TE=8 timesteps.
// grid (SEQ/TE, 2), block 160.
// ============================================================================
__global__ void __launch_bounds__(160) embZ_kernel(
    const int* __restrict__ sentence, const float* __restrict__ E,
    const float* __restrict__ Wk_f, const float* __restrict__ b_f,
    const float* __restrict__ Wk_b, const float* __restrict__ b_b)
{
    __shared__ float x_sh[TE][D_IN];
    const int t0  = blockIdx.x * TE;
    const int dir = blockIdx.y;

    for (int i = threadIdx.x; i < TE * D_IN; i += 160) {
        const int r = i / D_IN, d = i % D_IN;
        x_sh[r][d] = E[(size_t)sentence[t0 + r] * D_IN + d];
    }
    __syncthreads();

    const float* __restrict__ Wk = dir ? Wk_b : Wk_f;
    const float* __restrict__ b  = dir ? b_b  : b_f;

    const int j = threadIdx.x * 4;
    if (j < NZ) {
        const float4 bv = *(const float4*)(b + j);
        float4 acc[TE];
        #pragma unroll
        for (int r = 0; r < TE; r++) acc[r] = bv;

        #pragma unroll 2
        for (int d = 0; d < D_IN; d++) {
            const float4 wv = *(const float4*)(Wk + d * NZ + j);
            #pragma unroll
            for (int r = 0; r < TE; r++) {
                const float x = x_sh[r][d];
                acc[r].x = fmaf(x, wv.x, acc[r].x);
                acc[r].y = fmaf(x, wv.y, acc[r].y);
                acc[r].z = fmaf(x, wv.z, acc[r].z);
                acc[r].w = fmaf(x, wv.w, acc[r].w);
            }
        }
        #pragma unroll
        for (int r = 0; r < TE; r++)
            *(float4*)&g_Z[dir][t0 + r][j] = acc[r];
    }
}

// ============================================================================
// Kernel 2: sequential bidirectional LSTM recurrence — OUTPUT-SLICED over an
// 8-CTA cluster, SYNC-FREE inner loop (the R10 champion + MUFU sigmoid).
// grid (8, 2), cluster (8,1,1): blockIdx.y = direction.
// CTA rank r owns h-outputs [r*20, r*20+20) (rank7: 10 real + 10 pad) for ALL
// 4 gates: 160 threads = 20 outputs x 4 gates x 2 split-k halves. Gate
// exchange via intra-warp shfl; h delivered to all 8 CTAs (incl. self) via
// st.async.v4 + double-buffered mbarrier (tx count = the only sync).
// Fan-out 8 split across lane0 (ranks 0-3) and lane16 (ranks 4-7).
// Reuse safety: a peer can only overwrite my read-buffer after receiving all
// 640B for the next step, which includes my slowest warp's push, which
// postdates that warp's reads of the buffer.
// ============================================================================
__global__ void __cluster_dims__(NCTA, 1, 1) __launch_bounds__(160, 1)
lstm_rec_kernel(const float* __restrict__ Wr_f, const float* __restrict__ Wr_b)
{
    __shared__ __align__(16) float h_sh[2][KP];     // double-buffered hidden state
    __shared__ __align__(8)  unsigned long long mbar_sh[2];

    const int tid  = threadIdx.x;
    const int wrp  = tid >> 5;
    const int lane = tid & 31;
    const int u    = tid >> 1;         // unit 0..79
    const int kh   = tid & 1;          // k-half: 0 -> k[0..79], 1 -> k[80..159]
    const int g    = u & 3;            // gate 0=i 1=f 2=g 3=o
    const int o    = u >> 2;           // local output 0..19
    const uint32_t rank = my_cluster_rank();
    const int obase = rank * SLICE;
    const int myo   = obase + o;       // global output index
    const bool unit_act = (myo < U);
    const bool lead  = unit_act && (kh == 0);
    const bool cellT = lead && (g == 0);
    const int dir = blockIdx.y;
    const float* __restrict__ Wr = dir ? Wr_b : Wr_f;
    const int col = unit_act ? (g * U + myo) : 0;
    const uint32_t inbytes = KP * 4;   // 640B: all 8 ranks incl. self

    if (tid < KP) { h_sh[0][tid] = 0.f; h_sh[1][tid] = 0.f; }
    if (tid == 0) {
        mbar_init(smem_u32(&mbar_sh[0]), 1);
        mbar_init(smem_u32(&mbar_sh[1]), 1);
    }

    // register-resident weights (my k-half of Wr column `col`), f32x2 packed
    unsigned long long w2[W2N];
    #pragma unroll
    for (int jj = 0; jj < W2N; jj++) {
        const int k = kh * KH + 2 * jj;
        float wa = 0.f, wb = 0.f;
        if (unit_act && k     < U) wa = Wr[k * NZ + col];
        if (unit_act && k + 1 < U) wb = Wr[(k + 1) * NZ + col];
        w2[jj] = pack2(wa, wb);
    }

    // push targets: lane0 covers ranks 0-3, lane16 covers ranks 4-7.
    const uint32_t rbase = (lane >= 16) ? 4u : 0u;
    uint32_t pdst[2][4], pbar[2][4];
    {
        const uint32_t l0 = smem_u32(&h_sh[0][obase + 4 * wrp]);
        const uint32_t l1 = smem_u32(&h_sh[1][obase + 4 * wrp]);
        const uint32_t b0 = smem_u32(&mbar_sh[0]);
        const uint32_t b1 = smem_u32(&mbar_sh[1]);
        #pragma unroll
        for (uint32_t i = 0; i < 4; i++) {
            pdst[0][i] = mapa_rank(l0, rbase + i);
            pdst[1][i] = mapa_rank(l1, rbase + i);
            pbar[0][i] = mapa_rank(b0, rbase + i);
            pbar[1][i] = mapa_rank(b1, rbase + i);
        }
    }
    const uint32_t my_bar[2] = { smem_u32(&mbar_sh[0]), smem_u32(&mbar_sh[1]) };

    float c = 0.f;                 // cell state (cell threads only)
    int par[2] = { 0, 0 };         // phase parity per barrier
    __syncthreads();
    cluster_sync_();               // barriers + zeroed h live cluster-wide

    float zpre = lead ? __ldg(&g_Z[dir][dir ? (SEQ - 1) : 0][col]) : 0.f;
    const int lbase = lane & 24;   // base lane of my 8-lane output group
    const unsigned m = 0xffffffffu;

    for (int ti = 0; ti < SEQ; ti++) {
        const int t  = dir ? (SEQ - 1 - ti) : ti;
        const int b  = ti & 1;
        const int nb = b ^ 1;

        // the ONLY sync: wait for all 640B of this step's h (skip t=0: h=0)
        if (ti > 0) { mbar_wait_parity_cta(my_bar[b], par[b]); par[b] ^= 1; }
        // arm next buffer's barrier (tx counter tolerates early stores)
        if (tid == 0 && ti + 1 < SEQ) mbar_arrive_expect_tx(my_bar[nb], inbytes);

        // prefetch next step's Z (consumed next iteration -> latency hidden)
        float zn = 0.f;
        if (lead && ti + 1 < SEQ)
            zn = __ldg(&g_Z[dir][dir ? (SEQ - 2 - ti) : (ti + 1)][col]);

        // z = zpre + (my k-half of h) . w — u64 loads feed f32x2 FMA directly
        unsigned long long a0 = pack2(zpre, 0.f), a1 = pack2(0.f, 0.f);
        const ulonglong2* hp = (const ulonglong2*)&h_sh[b][kh * KH];
        #pragma unroll
        for (int j = 0; j < W2N / 2; j++) {
            const ulonglong2 hv = hp[j];
            fma2(a0, hv.x, w2[2 * j + 0]);
            fma2(a1, hv.y, w2[2 * j + 1]);
        }
        float f0, f1, f2, f3;
        unpack2(a0, f0, f1);
        unpack2(a1, f2, f3);
        float z = (f0 + f2) + (f1 + f3);
        z += __shfl_xor_sync(m, z, 1);    // combine k-halves

        // single-MUFU activation: sigmoid(x) = 0.5*tanh(0.5x)+0.5
        const float targ = (g == 2) ? z : 0.5f * z;
        const float tv   = tanh_approx(targ);
        const float a    = (g == 2) ? tv : fmaf(0.5f, tv, 0.5f);

        // intra-warp gate exchange: gates of output o sit at lanes lbase+2g
        const float af = __shfl_sync(m, a, lbase + 2);
        const float ag = __shfl_sync(m, a, lbase + 4);
        const float ao = __shfl_sync(m, a, lbase + 6);

        float hval = 0.f;          // pad lanes push 0.0 (tail stays zero)
        float cnew = c;
        if (cellT) {               // a == input gate here
            cnew = fmaf(af, c, a * ag);
            hval = ao * tanh_approx(cnew);
        }
        c = cnew;

        // warp-gather the 4 cell h values (lanes 0,8,16,24); push FIRST
        // (critical path), then the global store for downstream kernels.
        if (ti + 1 < SEQ) {
            const float vx = __shfl_sync(m, hval, 0);
            const float vy = __shfl_sync(m, hval, 8);
            const float vz = __shfl_sync(m, hval, 16);
            const float vw = __shfl_sync(m, hval, 24);
            if ((lane & 15) == 0) {
                st_async_v4(pdst[nb][0], vx, vy, vz, vw, pbar[nb][0]);
                st_async_v4(pdst[nb][1], vx, vy, vz, vw, pbar[nb][1]);
                st_async_v4(pdst[nb][2], vx, vy, vz, vw, pbar[nb][2]);
                st_async_v4(pdst[nb][3], vx, vy, vz, vw, pbar[nb][3]);
            }
        }
        if (cellT) g_hidden[t][dir * U + myo] = hval;
        zpre = zn;
    }
    cluster_sync_();               // keep peers alive until traffic retired
}

// ============================================================================
// Kernel 3: out = hidden @ W1 + b1, TT=4 rows per block (measured best).
// ============================================================================
__global__ void __launch_bounds__(320) outGemm_kernel(
    const float* __restrict__ W1, const float* __restrict__ b1)
{
    __shared__ float hrow[TT][H1];
    const int t0 = blockIdx.x * TT;
    for (int i = threadIdx.x; i < TT * H1; i += 320)
        hrow[i / H1][i % H1] = g_hidden[t0 + i / H1][i % H1];
    __syncthreads();

    const int j = threadIdx.x;
    if (j < H1) {
        const float bj = b1[j];
        float acc[TT];
        #pragma unroll
        for (int r = 0; r < TT; r++) acc[r] = bj;
        #pragma unroll 4
        for (int d = 0; d < H1; d++) {
            const float w = __ldg(&W1[d * H1 + j]);
            #pragma unroll
            for (int r = 0; r < TT; r++) acc[r] = fmaf(hrow[r][d], w, acc[r]);
        }
        #pragma unroll
        for (int r = 0; r < TT; r++) g_out[t0 + r][j] = acc[r];
    }
}

// ============================================================================
// Kernel 4: per-position synonym attention + h_hat + c2, accumulate H.
// grid SEQ, block 128 (warp k handles synonym k).
// ============================================================================
__global__ void __launch_bounds__(128) syn_kernel(
    const int* __restrict__ sentence, const int* __restrict__ syn,
    const float* __restrict__ E,
    const float* __restrict__ W2, const float* __restrict__ b2)
{
    __shared__ float orow[H1];
    __shared__ float hhat[H1];
    __shared__ float e_sh[4][H1];
    __shared__ float coeff_sh[4];
    __shared__ float red_sh[4];
    __shared__ float c2_sh;

    const int s    = blockIdx.x;
    const int idx  = s ? (s - 1) : 0;
    const int tid  = threadIdx.x;
    const int wid  = tid >> 5;
    const int lane = tid & 31;

    for (int d = tid; d < H1; d += 128) {
        orow[d] = g_out[idx][d];
        hhat[d] = g_hidden[idx][d];
    }
    __syncthreads();

    {
        const int tok = sentence[s];
        const float* __restrict__ e = E + (size_t)syn[tok * 4 + wid] * D_IN;
        float p = 0.f;
        for (int d = lane; d < H1; d += 32) {
            const float ev = e[d];
            e_sh[wid][d] = ev;
            p = fmaf(ev, orow[d], p);
        }
        #pragma unroll
        for (int o = 16; o > 0; o >>= 1) p += __shfl_xor_sync(0xffffffffu, p, o);
        if (lane == 0) coeff_sh[wid] = __expf(p);
    }
    __syncthreads();

    const float c0 = coeff_sh[0], c1 = coeff_sh[1], c2c = coeff_sh[2], c3 = coeff_sh[3];
    for (int d = tid; d < H1; d += 128) {
        float v = hhat[d];
        v = fmaf(c0, e_sh[0][d], v);
        v = fmaf(c1, e_sh[1][d], v);
        v = fmaf(c2c, e_sh[2][d], v);
        v = fmaf(c3, e_sh[3][d], v);
        hhat[d] = v;
    }
    __syncthreads();

    float p = 0.f;
    for (int d = tid; d < H1; d += 128) p = fmaf(hhat[d], W2[d], p);
    #pragma unroll
    for (int o = 16; o > 0; o >>= 1) p += __shfl_xor_sync(0xffffffffu, p, o);
    if (lane == 0) red_sh[wid] = p;
    __syncthreads();
    if (tid == 0)
        c2_sh = __expf(tanhf(red_sh[0] + red_sh[1] + red_sh[2] + red_sh[3] + b2[0]));
    __syncthreads();

    const float c2 = c2_sh;
    for (int d = tid; d < H1; d += 128) atomicAdd(&g_H[d], c2 * hhat[d]);
}

// ============================================================================
// Kernel 5: heads — out[0..7] = H@We + be, out[8] = H@Ws + bs
// ============================================================================
__global__ void heads_kernel(
    const float* __restrict__ We, const float* __restrict__ be,
    const float* __restrict__ Ws, const float* __restrict__ bs,
    float* __restrict__ out)
{
    const int j = threadIdx.x;
    if (j < 8) {
        float acc = be[j];
        for (int d = 0; d < H1; d++) acc = fmaf(g_H[d], We[d * 8 + j], acc);
        out[j] = acc;
    } else if (j == 8) {
        float acc = bs[0];
        for (int d = 0; d < H1; d++) acc = fmaf(g_H[d], Ws[d], acc);
        out[8] = acc;
    }
}

// ============================================================================
extern "C" void kernel_launch(void* const* d_in, const int* in_sizes, int n_in,
                              void* d_out, int out_size)
{
    const int*   sentence = (const int*)  d_in[0];
    const int*   syn      = (const int*)  d_in[1];
    const float* E        = (const float*)d_in[2];
    const float* Wk_f     = (const float*)d_in[3];
    const float* Wr_f     = (const float*)d_in[4];
    const float* b_f      = (const float*)d_in[5];
    const float* Wk_b     = (const float*)d_in[6];
    const float* Wr_b     = (const float*)d_in[7];
    const float* b_b      = (const float*)d_in[8];
    const float* W1       = (const float*)d_in[9];
    const float* b1       = (const float*)d_in[10];
    const float* W2       = (const float*)d_in[11];
    const float* b2       = (const float*)d_in[12];
    const float* We       = (const float*)d_in[13];
    const float* be       = (const float*)d_in[14];
    const float* Ws       = (const float*)d_in[15];
    const float* bs       = (const float*)d_in[16];
    float* out = (float*)d_out;

    zeroH_kernel<<<1, 320>>>();
    embZ_kernel<<<dim3(SEQ / TE, 2), 160>>>(sentence, E, Wk_f, b_f, Wk_b, b_b);
    lstm_rec_kernel<<<dim3(NCTA, 2), 160>>>(Wr_f, Wr_b);
    outGemm_kernel<<<SEQ / TT, 320>>>(W1, b1);
    syn_kernel<<<SEQ, 128>>>(sentence, syn, E, W2, b2);
    heads_kernel<<<1, 32>>>(We, be, Ws, bs, out);
}

// round 15
// speedup vs baseline: 2.0034x; 1.3655x over previous
#include <cuda_runtime.h>
#include <cuda_bf16.h>
#include <cstdint>

#define SEQ   2048
#define D_IN  300
#define U     150
#define NZ    600      // 4 gates * U
#define H1    300
#define TE    8        // timestep tile for embZ
#define TT    4        // timestep tile for outGemm (measured best)
#define NCTA  8        // cluster size (CTAs per direction); 8 = portable max
#define SLICE 20       // h-outputs owned per CTA rank (rank7: 10 real + 10 pad)
#define KP    160      // padded recurrence depth = NCTA*SLICE
#define KH    80       // split-k half depth
#define W2N   40       // f32x2 weights per thread (KH/2)
#define HALFB 320u     // bytes per half-barrier per step: 4 ranks * 5 warps * 16B

// ------------------------- scratch (static device memory; no allocs) ---------
__device__ float g_Z[2][SEQ][NZ];        // precomputed x@Wk + b, per direction
__device__ float g_hidden[SEQ][H1];      // [hf | hb] concat
__device__ float g_out[SEQ][H1];         // hidden @ W1 + b1
__device__ float g_H[H1];                // final weighted sum

// ------------------------- small PTX helpers ---------------------------------
__device__ __forceinline__ uint32_t smem_u32(const void* p) {
    return (uint32_t)__cvta_generic_to_shared(p);
}
__device__ __forceinline__ uint32_t mapa_rank(uint32_t addr, uint32_t r) {
    uint32_t out;
    asm("mapa.shared::cluster.u32 %0, %1, %2;" : "=r"(out) : "r"(addr), "r"(r));
    return out;
}
__device__ __forceinline__ void cluster_sync_() {
    asm volatile("barrier.cluster.arrive.aligned;" ::: "memory");
    asm volatile("barrier.cluster.wait.aligned;" ::: "memory");
}
__device__ __forceinline__ uint32_t my_cluster_rank() {
    uint32_t r;
    asm("mov.u32 %0, %%cluster_ctarank;" : "=r"(r));
    return r;
}
__device__ __forceinline__ unsigned long long pack2(float lo, float hi) {
    unsigned long long r;
    asm("mov.b64 %0, {%1, %2};" : "=l"(r) : "f"(lo), "f"(hi));
    return r;
}
__device__ __forceinline__ void fma2(unsigned long long& d, unsigned long long a,
                                     unsigned long long b) {
    asm("fma.rn.f32x2 %0, %1, %2, %0;" : "+l"(d) : "l"(a), "l"(b));
}
__device__ __forceinline__ void unpack2(unsigned long long v, float& lo, float& hi) {
    asm("mov.b64 {%0, %1}, %2;" : "=f"(lo), "=f"(hi) : "l"(v));
}
__device__ __forceinline__ float tanh_approx(float x) {
    float r;
    asm("tanh.approx.f32 %0, %1;" : "=f"(r) : "f"(x));
    return r;
}
__device__ __forceinline__ void mbar_init(uint32_t addr, uint32_t cnt) {
    asm volatile("mbarrier.init.shared.b64 [%0], %1;" :: "r"(addr), "r"(cnt) : "memory");
}
__device__ __forceinline__ void mbar_arrive_expect_tx(uint32_t addr, uint32_t tx) {
    asm volatile("mbarrier.arrive.expect_tx.shared.b64 _, [%0], %1;"
                 :: "r"(addr), "r"(tx) : "memory");
}
// CTA-scope acquire wait. DIVERGENCE-SAFE: adjacent lanes wait different
// half-barriers (kh = tid&1), so the try_wait predicate is NOT warp-uniform.
// Uses a plain (non-.uni) branch — bra.uni under a divergent predicate is UB
// and was the R13/R14 hang. Lanes reconverge at the next full-mask shfl.
__device__ __forceinline__ void mbar_wait_parity_cta(uint32_t addr, uint32_t parity) {
    asm volatile(
        "{\n\t"
        ".reg .pred P1;\n\t"
        "WAIT_LOOP_%=:\n\t"
        "mbarrier.try_wait.parity.acquire.cta.shared::cta.b64 P1, [%0], %1, 0x989680;\n\t"
        "@!P1 bra WAIT_LOOP_%=;\n\t"
        "}"
        :: "r"(addr), "r"(parity) : "memory");
}
// one 16-byte vector store, ONE complete_tx transaction at the target barrier
__device__ __forceinline__ void st_async_v4(uint32_t daddr, float x, float y,
                                            float z, float w, uint32_t mbar) {
    asm volatile(
        "st.async.shared::cluster.mbarrier::complete_tx::bytes.v4.b32 "
        "[%0], {%1, %2, %3, %4}, [%5];"
        :: "r"(daddr), "f"(x), "f"(y), "f"(z), "f"(w), "r"(mbar) : "memory");
}

// ============================================================================
// Kernel 0: zero the accumulator for H
// ============================================================================
__global__ void zeroH_kernel() {
    if (threadIdx.x < H1) g_H[threadIdx.x] = 0.f;
}

// ============================================================================
// Kernel 1: Z[dir][t][:] = x_t @ Wk + b, tiled over TE=8 timesteps.
// grid (SEQ/TE, 2), block 160.
// ============================================================================
__global__ void __launch_bounds__(160) embZ_kernel(
    const int* __restrict__ sentence, const float* __restrict__ E,
    const float* __restrict__ Wk_f, const float* __restrict__ b_f,
    const float* __restrict__ Wk_b, const float* __restrict__ b_b)
{
    __shared__ float x_sh[TE][D_IN];
    const int t0  = blockIdx.x * TE;
    const int dir = blockIdx.y;

    for (int i = threadIdx.x; i < TE * D_IN; i += 160) {
        const int r = i / D_IN, d = i % D_IN;
        x_sh[r][d] = E[(size_t)sentence[t0 + r] * D_IN + d];
    }
    __syncthreads();

    const float* __restrict__ Wk = dir ? Wk_b : Wk_f;
    const float* __restrict__ b  = dir ? b_b  : b_f;

    const int j = threadIdx.x * 4;
    if (j < NZ) {
        const float4 bv = *(const float4*)(b + j);
        float4 acc[TE];
        #pragma unroll
        for (int r = 0; r < TE; r++) acc[r] = bv;

        #pragma unroll 2
        for (int d = 0; d < D_IN; d++) {
            const float4 wv = *(const float4*)(Wk + d * NZ + j);
            #pragma unroll
            for (int r = 0; r < TE; r++) {
                const float x = x_sh[r][d];
                acc[r].x = fmaf(x, wv.x, acc[r].x);
                acc[r].y = fmaf(x, wv.y, acc[r].y);
                acc[r].z = fmaf(x, wv.z, acc[r].z);
                acc[r].w = fmaf(x, wv.w, acc[r].w);
            }
        }
        #pragma unroll
        for (int r = 0; r < TE; r++)
            *(float4*)&g_Z[dir][t0 + r][j] = acc[r];
    }
}

// ============================================================================
// Kernel 2: sequential bidirectional LSTM recurrence — OUTPUT-SLICED over an
// 8-CTA cluster, SYNC-FREE inner loop, SPLIT-HALF BARRIERS.
// grid (8, 2), cluster (8,1,1): blockIdx.y = direction.
// CTA rank r owns h-outputs [r*20, r*20+20) (rank7: 10 real + 10 pad) for ALL
// 4 gates. Gate exchange via intra-warp shfl; h delivered to all 8 CTAs
// (incl. self) via st.async.v4. Each buffer has TWO mbarriers: barL receives
// ranks 0-3's slices (h[0..79]) and barH ranks 4-7's (h[80..159]) — 20 tx
// accumulate in parallel on each instead of 40 serializing on one. A thread
// waits only its own k-half's barrier (divergent within the warp — wait loop
// must use non-uniform branches; lanes reconverge at the full-mask shfl).
// ARMING INVARIANT: a thread only arms a barrier it itself waits every step —
// tid0 (kh=0) arms half 0, tid1 (kh=1) arms half 1. The armer's wait at step
// ti-1 observed that half's phase flip, so the arm at step ti targets a fresh
// phase; no double-arrival is possible.
// Reuse safety: every peer's next step gates on BOTH its half-barriers, one
// of which counts my CTA's pushes, which postdate my warps' buffer reads.
// ============================================================================
__global__ void __cluster_dims__(NCTA, 1, 1) __launch_bounds__(160, 1)
lstm_rec_kernel(const float* __restrict__ Wr_f, const float* __restrict__ Wr_b)
{
    __shared__ __align__(16) float h_sh[2][KP];      // double-buffered hidden state
    __shared__ __align__(8)  unsigned long long mbar_sh[2][2];  // [buf][half]

    const int tid  = threadIdx.x;
    const int wrp  = tid >> 5;
    const int lane = tid & 31;
    const int u    = tid >> 1;         // unit 0..79
    const int kh   = tid & 1;          // k-half: 0 -> k[0..79], 1 -> k[80..159]
    const int g    = u & 3;            // gate 0=i 1=f 2=g 3=o
    const int o    = u >> 2;           // local output 0..19
    const uint32_t rank = my_cluster_rank();
    const int obase = rank * SLICE;
    const int myo   = obase + o;       // global output index
    const bool unit_act = (myo < U);
    const bool lead  = unit_act && (kh == 0);
    const bool cellT = lead && (g == 0);
    const int dir = blockIdx.y;
    const float* __restrict__ Wr = dir ? Wr_b : Wr_f;
    const int col = unit_act ? (g * U + myo) : 0;
    const uint32_t myhalf = (rank >= 4) ? 1u : 0u;   // which half my slice feeds

    if (tid < KP) { h_sh[0][tid] = 0.f; h_sh[1][tid] = 0.f; }
    if (tid == 0) {
        mbar_init(smem_u32(&mbar_sh[0][0]), 1);
        mbar_init(smem_u32(&mbar_sh[0][1]), 1);
        mbar_init(smem_u32(&mbar_sh[1][0]), 1);
        mbar_init(smem_u32(&mbar_sh[1][1]), 1);
    }

    // register-resident weights (my k-half of Wr column `col`), f32x2 packed
    unsigned long long w2[W2N];
    #pragma unroll
    for (int jj = 0; jj < W2N; jj++) {
        const int k = kh * KH + 2 * jj;
        float wa = 0.f, wb = 0.f;
        if (unit_act && k     < U) wa = Wr[k * NZ + col];
        if (unit_act && k + 1 < U) wb = Wr[(k + 1) * NZ + col];
        w2[jj] = pack2(wa, wb);
    }

    // push targets: lane0 covers ranks 0-3, lane16 covers ranks 4-7.
    // All pushes from this CTA land in the destination's half-barrier `myhalf`.
    const uint32_t rbase = (lane >= 16) ? 4u : 0u;
    uint32_t pdst[2][4], pbar[2][4];
    {
        const uint32_t l0 = smem_u32(&h_sh[0][obase + 4 * wrp]);
        const uint32_t l1 = smem_u32(&h_sh[1][obase + 4 * wrp]);
        const uint32_t b0 = smem_u32(&mbar_sh[0][myhalf]);
        const uint32_t b1 = smem_u32(&mbar_sh[1][myhalf]);
        #pragma unroll
        for (uint32_t i = 0; i < 4; i++) {
            pdst[0][i] = mapa_rank(l0, rbase + i);
            pdst[1][i] = mapa_rank(l1, rbase + i);
            pbar[0][i] = mapa_rank(b0, rbase + i);
            pbar[1][i] = mapa_rank(b1, rbase + i);
        }
    }
    // wait address: my k-half's barrier in each buffer (kh matches arm duty)
    const uint32_t my_bar[2] = { smem_u32(&mbar_sh[0][kh]),
                                 smem_u32(&mbar_sh[1][kh]) };

    float c = 0.f;                 // cell state (cell threads only)
    int par[2] = { 0, 0 };         // phase parity per buffer (own half)
    __syncthreads();
    cluster_sync_();               // barriers + zeroed h live cluster-wide

    float zpre = lead ? __ldg(&g_Z[dir][dir ? (SEQ - 1) : 0][col]) : 0.f;
    const int lbase = lane & 24;   // base lane of my 8-lane output group
    const unsigned m = 0xffffffffu;

    for (int ti = 0; ti < SEQ; ti++) {
        const int t  = dir ? (SEQ - 1 - ti) : ti;
        const int b  = ti & 1;
        const int nb = b ^ 1;

        // arm next buffer's half-barriers: tid0 arms half0, tid1 arms half1.
        // Each armer waited its own half at step ti-1, so the phase is fresh.
        if (tid < 2 && ti + 1 < SEQ)
            mbar_arrive_expect_tx(my_bar[nb], HALFB);

        // the ONLY sync: wait for my k-half of this step's h (skip t=0: h=0)
        if (ti > 0) { mbar_wait_parity_cta(my_bar[b], par[b]); par[b] ^= 1; }

        // prefetch next step's Z (consumed next iteration -> latency hidden)
        float zn = 0.f;
        if (lead && ti + 1 < SEQ)
            zn = __ldg(&g_Z[dir][dir ? (SEQ - 2 - ti) : (ti + 1)][col]);

        // z = zpre + (my k-half of h) . w — u64 loads feed f32x2 FMA directly
        unsigned long long a0 = pack2(zpre, 0.f), a1 = pack2(0.f, 0.f);
        const ulonglong2* hp = (const ulonglong2*)&h_sh[b][kh * KH];
        #pragma unroll
        for (int j = 0; j < W2N / 2; j++) {
            const ulonglong2 hv = hp[j];
            fma2(a0, hv.x, w2[2 * j + 0]);
            fma2(a1, hv.y, w2[2 * j + 1]);
        }
        float f0, f1, f2, f3;
        unpack2(a0, f0, f1);
        unpack2(a1, f2, f3);
        float z = (f0 + f2) + (f1 + f3);
        z += __shfl_xor_sync(m, z, 1);    // combine k-halves (reconverges warp)

        // single-MUFU activation: sigmoid(x) = 0.5*tanh(0.5x)+0.5
        const float targ = (g == 2) ? z : 0.5f * z;
        const float tv   = tanh_approx(targ);
        const float a    = (g == 2) ? tv : fmaf(0.5f, tv, 0.5f);

        // intra-warp gate exchange: gates of output o sit at lanes lbase+2g
        const float af = __shfl_sync(m, a, lbase + 2);
        const float ag = __shfl_sync(m, a, lbase + 4);
        const float ao = __shfl_sync(m, a, lbase + 6);

        float hval = 0.f;          // pad lanes push 0.0 (tail stays zero)
        float cnew = c;
        if (cellT) {               // a == input gate here
            cnew = fmaf(af, c, a * ag);
            hval = ao * tanh_approx(cnew);
        }
        c = cnew;

        // warp-gather the 4 cell h values (lanes 0,8,16,24); push FIRST
        // (critical path), then the global store for downstream kernels.
        if (ti + 1 < SEQ) {
            const float vx = __shfl_sync(m, hval, 0);
            const float vy = __shfl_sync(m, hval, 8);
            const float vz = __shfl_sync(m, hval, 16);
            const float vw = __shfl_sync(m, hval, 24);
            if ((lane & 15) == 0) {
                st_async_v4(pdst[nb][0], vx, vy, vz, vw, pbar[nb][0]);
                st_async_v4(pdst[nb][1], vx, vy, vz, vw, pbar[nb][1]);
                st_async_v4(pdst[nb][2], vx, vy, vz, vw, pbar[nb][2]);
                st_async_v4(pdst[nb][3], vx, vy, vz, vw, pbar[nb][3]);
            }
        }
        if (cellT) g_hidden[t][dir * U + myo] = hval;
        zpre = zn;
    }
    cluster_sync_();               // keep peers alive until traffic retired
}

// ============================================================================
// Kernel 3: out = hidden @ W1 + b1, TT=4 rows per block (measured best).
// ============================================================================
__global__ void __launch_bounds__(320) outGemm_kernel(
    const float* __restrict__ W1, const float* __restrict__ b1)
{
    __shared__ float hrow[TT][H1];
    const int t0 = blockIdx.x * TT;
    for (int i = threadIdx.x; i < TT * H1; i += 320)
        hrow[i / H1][i % H1] = g_hidden[t0 + i / H1][i % H1];
    __syncthreads();

    const int j = threadIdx.x;
    if (j < H1) {
        const float bj = b1[j];
        float acc[TT];
        #pragma unroll
        for (int r = 0; r < TT; r++) acc[r] = bj;
        #pragma unroll 4
        for (int d = 0; d < H1; d++) {
            const float w = __ldg(&W1[d * H1 + j]);
            #pragma unroll
            for (int r = 0; r < TT; r++) acc[r] = fmaf(hrow[r][d], w, acc[r]);
        }
        #pragma unroll
        for (int r = 0; r < TT; r++) g_out[t0 + r][j] = acc[r];
    }
}

// ============================================================================
// Kernel 4: per-position synonym attention + h_hat + c2, accumulate H.
// grid SEQ, block 128 (warp k handles synonym k).
// ============================================================================
__global__ void __launch_bounds__(128) syn_kernel(
    const int* __restrict__ sentence, const int* __restrict__ syn,
    const float* __restrict__ E,
    const float* __restrict__ W2, const float* __restrict__ b2)
{
    __shared__ float orow[H1];
    __shared__ float hhat[H1];
    __shared__ float e_sh[4][H1];
    __shared__ float coeff_sh[4];
    __shared__ float red_sh[4];
    __shared__ float c2_sh;

    const int s    = blockIdx.x;
    const int idx  = s ? (s - 1) : 0;
    const int tid  = threadIdx.x;
    const int wid  = tid >> 5;
    const int lane = tid & 31;

    for (int d = tid; d < H1; d += 128) {
        orow[d] = g_out[idx][d];
        hhat[d] = g_hidden[idx][d];
    }
    __syncthreads();

    {
        const int tok = sentence[s];
        const float* __restrict__ e = E + (size_t)syn[tok * 4 + wid] * D_IN;
        float p = 0.f;
        for (int d = lane; d < H1; d += 32) {
            const float ev = e[d];
            e_sh[wid][d] = ev;
            p = fmaf(ev, orow[d], p);
        }
        #pragma unroll
        for (int o = 16; o > 0; o >>= 1) p += __shfl_xor_sync(0xffffffffu, p, o);
        if (lane == 0) coeff_sh[wid] = __expf(p);
    }
    __syncthreads();

    const float c0 = coeff_sh[0], c1 = coeff_sh[1], c2c = coeff_sh[2], c3 = coeff_sh[3];
    for (int d = tid; d < H1; d += 128) {
        float v = hhat[d];
        v = fmaf(c0, e_sh[0][d], v);
        v = fmaf(c1, e_sh[1][d], v);
        v = fmaf(c2c, e_sh[2][d], v);
        v = fmaf(c3, e_sh[3][d], v);
        hhat[d] = v;
    }
    __syncthreads();

    float p = 0.f;
    for (int d = tid; d < H1; d += 128) p = fmaf(hhat[d], W2[d], p);
    #pragma unroll
    for (int o = 16; o > 0; o >>= 1) p += __shfl_xor_sync(0xffffffffu, p, o);
    if (lane == 0) red_sh[wid] = p;
    __syncthreads();
    if (tid == 0)
        c2_sh = __expf(tanhf(red_sh[0] + red_sh[1] + red_sh[2] + red_sh[3] + b2[0]));
    __syncthreads();

    const float c2 = c2_sh;
    for (int d = tid; d < H1; d += 128) atomicAdd(&g_H[d], c2 * hhat[d]);
}

// ============================================================================
// Kernel 5: heads — out[0..7] = H@We + be, out[8] = H@Ws + bs
// ============================================================================
__global__ void heads_kernel(
    const float* __restrict__ We, const float* __restrict__ be,
    const float* __restrict__ Ws, const float* __restrict__ bs,
    float* __restrict__ out)
{
    const int j = threadIdx.x;
    if (j < 8) {
        float acc = be[j];
        for (int d = 0; d < H1; d++) acc = fmaf(g_H[d], We[d * 8 + j], acc);
        out[j] = acc;
    } else if (j == 8) {
        float acc = bs[0];
        for (int d = 0; d < H1; d++) acc = fmaf(g_H[d], Ws[d], acc);
        out[8] = acc;
    }
}

// ============================================================================
extern "C" void kernel_launch(void* const* d_in, const int* in_sizes, int n_in,
                              void* d_out, int out_size)
{
    const int*   sentence = (const int*)  d_in[0];
    const int*   syn      = (const int*)  d_in[1];
    const float* E        = (const float*)d_in[2];
    const float* Wk_f     = (const float*)d_in[3];
    const float* Wr_f     = (const float*)d_in[4];
    const float* b_f      = (const float*)d_in[5];
    const float* Wk_b     = (const float*)d_in[6];
    const float* Wr_b     = (const float*)d_in[7];
    const float* b_b      = (const float*)d_in[8];
    const float* W1       = (const float*)d_in[9];
    const float* b1       = (const float*)d_in[10];
    const float* W2       = (const float*)d_in[11];
    const float* b2       = (const float*)d_in[12];
    const float* We       = (const float*)d_in[13];
    const float* be       = (const float*)d_in[14];
    const float* Ws       = (const float*)d_in[15];
    const float* bs       = (const float*)d_in[16];
    float* out = (float*)d_out;

    zeroH_kernel<<<1, 320>>>();
    embZ_kernel<<<dim3(SEQ / TE, 2), 160>>>(sentence, E, Wk_f, b_f, Wk_b, b_b);
    lstm_rec_kernel<<<dim3(NCTA, 2), 160>>>(Wr_f, Wr_b);
    outGemm_kernel<<<SEQ / TT, 320>>>(W1, b1);
    syn_kernel<<<SEQ, 128>>>(sentence, syn, E, W2, b2);
    heads_kernel<<<1, 32>>>(We, be, Ws, bs, out);
}

// round 16
// speedup vs baseline: 2.0781x; 1.0373x over previous
#include <cuda_runtime.h>
#include <cuda_bf16.h>
#include <cstdint>

#define SEQ   2048
#define D_IN  300
#define U     150
#define NZ    600      // 4 gates * U
#define H1    300
#define TE    16       // timestep tile for embZ (one wave at grid 128)
#define TT    4        // timestep tile for outGemm (measured best)
#define NCTA  8        // cluster size (CTAs per direction); 8 = portable max
#define SLICE 20       // h-outputs owned per CTA rank (rank7: 10 real + 10 pad)
#define KP    160      // padded recurrence depth = NCTA*SLICE
#define KH    80       // split-k half depth
#define W2N   40       // f32x2 weights per thread (KH/2)
#define HALFB 320u     // bytes per half-barrier per step: 4 ranks * 5 warps * 16B

// ------------------------- scratch (static device memory; no allocs) ---------
__device__ float g_Z[2][SEQ][NZ];        // precomputed x@Wk + b, per direction
__device__ float g_hidden[SEQ][H1];      // [hf | hb] concat
__device__ float g_out[SEQ][H1];         // hidden @ W1 + b1
__device__ float g_H[H1];                // final weighted sum

// ------------------------- small PTX helpers ---------------------------------
__device__ __forceinline__ uint32_t smem_u32(const void* p) {
    return (uint32_t)__cvta_generic_to_shared(p);
}
__device__ __forceinline__ uint32_t mapa_rank(uint32_t addr, uint32_t r) {
    uint32_t out;
    asm("mapa.shared::cluster.u32 %0, %1, %2;" : "=r"(out) : "r"(addr), "r"(r));
    return out;
}
__device__ __forceinline__ void cluster_sync_() {
    asm volatile("barrier.cluster.arrive.aligned;" ::: "memory");
    asm volatile("barrier.cluster.wait.aligned;" ::: "memory");
}
__device__ __forceinline__ uint32_t my_cluster_rank() {
    uint32_t r;
    asm("mov.u32 %0, %%cluster_ctarank;" : "=r"(r));
    return r;
}
__device__ __forceinline__ unsigned long long pack2(float lo, float hi) {
    unsigned long long r;
    asm("mov.b64 %0, {%1, %2};" : "=l"(r) : "f"(lo), "f"(hi));
    return r;
}
__device__ __forceinline__ void fma2(unsigned long long& d, unsigned long long a,
                                     unsigned long long b) {
    asm("fma.rn.f32x2 %0, %1, %2, %0;" : "+l"(d) : "l"(a), "l"(b));
}
__device__ __forceinline__ void unpack2(unsigned long long v, float& lo, float& hi) {
    asm("mov.b64 {%0, %1}, %2;" : "=f"(lo), "=f"(hi) : "l"(v));
}
__device__ __forceinline__ float tanh_approx(float x) {
    float r;
    asm("tanh.approx.f32 %0, %1;" : "=f"(r) : "f"(x));
    return r;
}
__device__ __forceinline__ void mbar_init(uint32_t addr, uint32_t cnt) {
    asm volatile("mbarrier.init.shared.b64 [%0], %1;" :: "r"(addr), "r"(cnt) : "memory");
}
__device__ __forceinline__ void mbar_arrive_expect_tx(uint32_t addr, uint32_t tx) {
    asm volatile("mbarrier.arrive.expect_tx.shared.b64 _, [%0], %1;"
                 :: "r"(addr), "r"(tx) : "memory");
}
// CTA-scope acquire wait. DIVERGENCE-SAFE: adjacent lanes wait different
// half-barriers (kh = tid&1), so the try_wait predicate is NOT warp-uniform.
// Uses a plain (non-.uni) branch — bra.uni under a divergent predicate is UB
// and was the R13/R14 hang. Lanes reconverge at the next full-mask shfl.
__device__ __forceinline__ void mbar_wait_parity_cta(uint32_t addr, uint32_t parity) {
    asm volatile(
        "{\n\t"
        ".reg .pred P1;\n\t"
        "WAIT_LOOP_%=:\n\t"
        "mbarrier.try_wait.parity.acquire.cta.shared::cta.b64 P1, [%0], %1, 0x989680;\n\t"
        "@!P1 bra WAIT_LOOP_%=;\n\t"
        "}"
        :: "r"(addr), "r"(parity) : "memory");
}
// one 16-byte vector store, ONE complete_tx transaction at the target barrier
__device__ __forceinline__ void st_async_v4(uint32_t daddr, float x, float y,
                                            float z, float w, uint32_t mbar) {
    asm volatile(
        "st.async.shared::cluster.mbarrier::complete_tx::bytes.v4.b32 "
        "[%0], {%1, %2, %3, %4}, [%5];"
        :: "r"(daddr), "f"(x), "f"(y), "f"(z), "f"(w), "r"(mbar) : "memory");
}

// ============================================================================
// Kernel 0: zero the accumulator for H
// ============================================================================
__global__ void zeroH_kernel() {
    if (threadIdx.x < H1) g_H[threadIdx.x] = 0.f;
}

// ============================================================================
// Kernel 1: Z[dir][t][:] = x_t @ Wk + b, tiled over TE=16 timesteps.
// grid (SEQ/16 = 128, 2) -> one wave on 148 SMs; Wk L2 traffic halved vs TE=8.
// ============================================================================
__global__ void __launch_bounds__(160) embZ_kernel(
    const int* __restrict__ sentence, const float* __restrict__ E,
    const float* __restrict__ Wk_f, const float* __restrict__ b_f,
    const float* __restrict__ Wk_b, const float* __restrict__ b_b)
{
    __shared__ float x_sh[TE][D_IN];
    const int t0  = blockIdx.x * TE;
    const int dir = blockIdx.y;

    for (int i = threadIdx.x; i < TE * D_IN; i += 160) {
        const int r = i / D_IN, d = i % D_IN;
        x_sh[r][d] = E[(size_t)sentence[t0 + r] * D_IN + d];
    }
    __syncthreads();

    const float* __restrict__ Wk = dir ? Wk_b : Wk_f;
    const float* __restrict__ b  = dir ? b_b  : b_f;

    const int j = threadIdx.x * 4;
    if (j < NZ) {
        const float4 bv = *(const float4*)(b + j);
        float4 acc[TE];
        #pragma unroll
        for (int r = 0; r < TE; r++) acc[r] = bv;

        #pragma unroll 2
        for (int d = 0; d < D_IN; d++) {
            const float4 wv = *(const float4*)(Wk + d * NZ + j);
            #pragma unroll
            for (int r = 0; r < TE; r++) {
                const float x = x_sh[r][d];
                acc[r].x = fmaf(x, wv.x, acc[r].x);
                acc[r].y = fmaf(x, wv.y, acc[r].y);
                acc[r].z = fmaf(x, wv.z, acc[r].z);
                acc[r].w = fmaf(x, wv.w, acc[r].w);
            }
        }
        #pragma unroll
        for (int r = 0; r < TE; r++)
            *(float4*)&g_Z[dir][t0 + r][j] = acc[r];
    }
}

// ============================================================================
// Kernel 2: sequential bidirectional LSTM recurrence — OUTPUT-SLICED over an
// 8-CTA cluster, SYNC-FREE inner loop, SPLIT-HALF BARRIERS (R15 champion).
// grid (8, 2), cluster (8,1,1): blockIdx.y = direction.
// CTA rank r owns h-outputs [r*20, r*20+20) (rank7: 10 real + 10 pad) for ALL
// 4 gates. Gate exchange via intra-warp shfl; h delivered to all 8 CTAs
// (incl. self) via st.async.v4. Each buffer has TWO mbarriers: barL receives
// ranks 0-3's slices (h[0..79]) and barH ranks 4-7's (h[80..159]) — 20 tx
// accumulate in parallel on each. A thread waits only its own k-half's
// barrier (divergent within the warp — wait loop uses non-uniform branches;
// lanes reconverge at the full-mask shfl).
// ARMING INVARIANT: a thread only arms a barrier it itself waits every step —
// tid0 (kh=0) arms half 0, tid1 (kh=1) arms half 1.
// Push fan-out spread over lanes 0,8,16,24 (2 destination ranks each).
// Reuse safety: every peer's next step gates on BOTH its half-barriers, one
// of which counts my CTA's pushes, which postdate my warps' buffer reads.
// ============================================================================
__global__ void __cluster_dims__(NCTA, 1, 1) __launch_bounds__(160, 1)
lstm_rec_kernel(const float* __restrict__ Wr_f, const float* __restrict__ Wr_b)
{
    __shared__ __align__(16) float h_sh[2][KP];      // double-buffered hidden state
    __shared__ __align__(8)  unsigned long long mbar_sh[2][2];  // [buf][half]

    const int tid  = threadIdx.x;
    const int wrp  = tid >> 5;
    const int lane = tid & 31;
    const int u    = tid >> 1;         // unit 0..79
    const int kh   = tid & 1;          // k-half: 0 -> k[0..79], 1 -> k[80..159]
    const int g    = u & 3;            // gate 0=i 1=f 2=g 3=o
    const int o    = u >> 2;           // local output 0..19
    const uint32_t rank = my_cluster_rank();
    const int obase = rank * SLICE;
    const int myo   = obase + o;       // global output index
    const bool unit_act = (myo < U);
    const bool lead  = unit_act && (kh == 0);
    const bool cellT = lead && (g == 0);
    const int dir = blockIdx.y;
    const float* __restrict__ Wr = dir ? Wr_b : Wr_f;
    const int col = unit_act ? (g * U + myo) : 0;
    const uint32_t myhalf = (rank >= 4) ? 1u : 0u;   // which half my slice feeds

    if (tid < KP) { h_sh[0][tid] = 0.f; h_sh[1][tid] = 0.f; }
    if (tid == 0) {
        mbar_init(smem_u32(&mbar_sh[0][0]), 1);
        mbar_init(smem_u32(&mbar_sh[0][1]), 1);
        mbar_init(smem_u32(&mbar_sh[1][0]), 1);
        mbar_init(smem_u32(&mbar_sh[1][1]), 1);
    }

    // register-resident weights (my k-half of Wr column `col`), f32x2 packed
    unsigned long long w2[W2N];
    #pragma unroll
    for (int jj = 0; jj < W2N; jj++) {
        const int k = kh * KH + 2 * jj;
        float wa = 0.f, wb = 0.f;
        if (unit_act && k     < U) wa = Wr[k * NZ + col];
        if (unit_act && k + 1 < U) wb = Wr[(k + 1) * NZ + col];
        w2[jj] = pack2(wa, wb);
    }

    // push targets: lanes 0,8,16,24 each cover TWO destination ranks
    // (lane>>3)*2 + {0,1}. All pushes from this CTA land in the destination's
    // half-barrier `myhalf`.
    const uint32_t rbase = (lane >> 3) * 2;          // 0,2,4,6
    uint32_t pdst[2][2], pbar[2][2];
    {
        const uint32_t l0 = smem_u32(&h_sh[0][obase + 4 * wrp]);
        const uint32_t l1 = smem_u32(&h_sh[1][obase + 4 * wrp]);
        const uint32_t b0 = smem_u32(&mbar_sh[0][myhalf]);
        const uint32_t b1 = smem_u32(&mbar_sh[1][myhalf]);
        #pragma unroll
        for (uint32_t i = 0; i < 2; i++) {
            pdst[0][i] = mapa_rank(l0, rbase + i);
            pdst[1][i] = mapa_rank(l1, rbase + i);
            pbar[0][i] = mapa_rank(b0, rbase + i);
            pbar[1][i] = mapa_rank(b1, rbase + i);
        }
    }
    // wait address: my k-half's barrier in each buffer (kh matches arm duty)
    const uint32_t my_bar[2] = { smem_u32(&mbar_sh[0][kh]),
                                 smem_u32(&mbar_sh[1][kh]) };

    float c = 0.f;                 // cell state (cell threads only)
    int par[2] = { 0, 0 };         // phase parity per buffer (own half)
    __syncthreads();
    cluster_sync_();               // barriers + zeroed h live cluster-wide

    float zpre = lead ? __ldg(&g_Z[dir][dir ? (SEQ - 1) : 0][col]) : 0.f;
    const int lbase = lane & 24;   // base lane of my 8-lane output group
    const unsigned m = 0xffffffffu;

    for (int ti = 0; ti < SEQ; ti++) {
        const int t  = dir ? (SEQ - 1 - ti) : ti;
        const int b  = ti & 1;
        const int nb = b ^ 1;

        // arm next buffer's half-barriers: tid0 arms half0, tid1 arms half1.
        // Each armer waited its own half at step ti-1, so the phase is fresh.
        if (tid < 2 && ti + 1 < SEQ)
            mbar_arrive_expect_tx(my_bar[nb], HALFB);

        // prefetch next step's Z BEFORE the wait (no h dependency; LDG
        // latency overlaps the spin instead of the dot window)
        float zn = 0.f;
        if (lead && ti + 1 < SEQ)
            zn = __ldg(&g_Z[dir][dir ? (SEQ - 2 - ti) : (ti + 1)][col]);

        // the ONLY sync: wait for my k-half of this step's h (skip t=0: h=0)
        if (ti > 0) { mbar_wait_parity_cta(my_bar[b], par[b]); par[b] ^= 1; }

        // z = zpre + (my k-half of h) . w — u64 loads feed f32x2 FMA directly
        unsigned long long a0 = pack2(zpre, 0.f), a1 = pack2(0.f, 0.f);
        const ulonglong2* hp = (const ulonglong2*)&h_sh[b][kh * KH];
        #pragma unroll
        for (int j = 0; j < W2N / 2; j++) {
            const ulonglong2 hv = hp[j];
            fma2(a0, hv.x, w2[2 * j + 0]);
            fma2(a1, hv.y, w2[2 * j + 1]);
        }
        float f0, f1, f2, f3;
        unpack2(a0, f0, f1);
        unpack2(a1, f2, f3);
        float z = (f0 + f2) + (f1 + f3);
        z += __shfl_xor_sync(m, z, 1);    // combine k-halves (reconverges warp)

        // single-MUFU activation: sigmoid(x) = 0.5*tanh(0.5x)+0.5
        const float targ = (g == 2) ? z : 0.5f * z;
        const float tv   = tanh_approx(targ);
        const float a    = (g == 2) ? tv : fmaf(0.5f, tv, 0.5f);

        // intra-warp gate exchange: gates of output o sit at lanes lbase+2g
        const float af = __shfl_sync(m, a, lbase + 2);
        const float ag = __shfl_sync(m, a, lbase + 4);
        const float ao = __shfl_sync(m, a, lbase + 6);

        float hval = 0.f;          // pad lanes push 0.0 (tail stays zero)
        float cnew = c;
        if (cellT) {               // a == input gate here
            cnew = fmaf(af, c, a * ag);
            hval = ao * tanh_approx(cnew);
        }
        c = cnew;

        // warp-gather the 4 cell h values (lanes 0,8,16,24); push FIRST
        // (critical path) — lanes 0,8,16,24 each push 2 destinations.
        if (ti + 1 < SEQ) {
            const float vx = __shfl_sync(m, hval, 0);
            const float vy = __shfl_sync(m, hval, 8);
            const float vz = __shfl_sync(m, hval, 16);
            const float vw = __shfl_sync(m, hval, 24);
            if ((lane & 7) == 0) {
                st_async_v4(pdst[nb][0], vx, vy, vz, vw, pbar[nb][0]);
                st_async_v4(pdst[nb][1], vx, vy, vz, vw, pbar[nb][1]);
            }
        }
        if (cellT) g_hidden[t][dir * U + myo] = hval;
        zpre = zn;
    }
    cluster_sync_();               // keep peers alive until traffic retired
}

// ============================================================================
// Kernel 3: out = hidden @ W1 + b1, TT=4 rows per block (measured best).
// ============================================================================
__global__ void __launch_bounds__(320) outGemm_kernel(
    const float* __restrict__ W1, const float* __restrict__ b1)
{
    __shared__ float hrow[TT][H1];
    const int t0 = blockIdx.x * TT;
    for (int i = threadIdx.x; i < TT * H1; i += 320)
        hrow[i / H1][i % H1] = g_hidden[t0 + i / H1][i % H1];
    __syncthreads();

    const int j = threadIdx.x;
    if (j < H1) {
        const float bj = b1[j];
        float acc[TT];
        #pragma unroll
        for (int r = 0; r < TT; r++) acc[r] = bj;
        #pragma unroll 4
        for (int d = 0; d < H1; d++) {
            const float w = __ldg(&W1[d * H1 + j]);
            #pragma unroll
            for (int r = 0; r < TT; r++) acc[r] = fmaf(hrow[r][d], w, acc[r]);
        }
        #pragma unroll
        for (int r = 0; r < TT; r++) g_out[t0 + r][j] = acc[r];
    }
}

// ============================================================================
// Kernel 4: per-position synonym attention + h_hat + c2, accumulate H.
// grid SEQ, block 128 (warp k handles synonym k).
// ============================================================================
__global__ void __launch_bounds__(128) syn_kernel(
    const int* __restrict__ sentence, const int* __restrict__ syn,
    const float* __restrict__ E,
    const float* __restrict__ W2, const float* __restrict__ b2)
{
    __shared__ float orow[H1];
    __shared__ float hhat[H1];
    __shared__ float e_sh[4][H1];
    __shared__ float coeff_sh[4];
    __shared__ float red_sh[4];
    __shared__ float c2_sh;

    const int s    = blockIdx.x;
    const int idx  = s ? (s - 1) : 0;
    const int tid  = threadIdx.x;
    const int wid  = tid >> 5;
    const int lane = tid & 31;

    for (int d = tid; d < H1; d += 128) {
        orow[d] = g_out[idx][d];
        hhat[d] = g_hidden[idx][d];
    }
    __syncthreads();

    {
        const int tok = sentence[s];
        const float* __restrict__ e = E + (size_t)syn[tok * 4 + wid] * D_IN;
        float p = 0.f;
        for (int d = lane; d < H1; d += 32) {
            const float ev = e[d];
            e_sh[wid][d] = ev;
            p = fmaf(ev, orow[d], p);
        }
        #pragma unroll
        for (int o = 16; o > 0; o >>= 1) p += __shfl_xor_sync(0xffffffffu, p, o);
        if (lane == 0) coeff_sh[wid] = __expf(p);
    }
    __syncthreads();

    const float c0 = coeff_sh[0], c1 = coeff_sh[1], c2c = coeff_sh[2], c3 = coeff_sh[3];
    for (int d = tid; d < H1; d += 128) {
        float v = hhat[d];
        v = fmaf(c0, e_sh[0][d], v);
        v = fmaf(c1, e_sh[1][d], v);
        v = fmaf(c2c, e_sh[2][d], v);
        v = fmaf(c3, e_sh[3][d], v);
        hhat[d] = v;
    }
    __syncthreads();

    float p = 0.f;
    for (int d = tid; d < H1; d += 128) p = fmaf(hhat[d], W2[d], p);
    #pragma unroll
    for (int o = 16; o > 0; o >>= 1) p += __shfl_xor_sync(0xffffffffu, p, o);
    if (lane == 0) red_sh[wid] = p;
    __syncthreads();
    if (tid == 0)
        c2_sh = __expf(tanhf(red_sh[0] + red_sh[1] + red_sh[2] + red_sh[3] + b2[0]));
    __syncthreads();

    const float c2 = c2_sh;
    for (int d = tid; d < H1; d += 128) atomicAdd(&g_H[d], c2 * hhat[d]);
}

// ============================================================================
// Kernel 5: heads — out[0..7] = H@We + be, out[8] = H@Ws + bs
// ============================================================================
__global__ void heads_kernel(
    const float* __restrict__ We, const float* __restrict__ be,
    const float* __restrict__ Ws, const float* __restrict__ bs,
    float* __restrict__ out)
{
    const int j = threadIdx.x;
    if (j < 8) {
        float acc = be[j];
        for (int d = 0; d < H1; d++) acc = fmaf(g_H[d], We[d * 8 + j], acc);
        out[j] = acc;
    } else if (j == 8) {
        float acc = bs[0];
        for (int d = 0; d < H1; d++) acc = fmaf(g_H[d], Ws[d], acc);
        out[8] = acc;
    }
}

// ============================================================================
extern "C" void kernel_launch(void* const* d_in, const int* in_sizes, int n_in,
                              void* d_out, int out_size)
{
    const int*   sentence = (const int*)  d_in[0];
    const int*   syn      = (const int*)  d_in[1];
    const float* E        = (const float*)d_in[2];
    const float* Wk_f     = (const float*)d_in[3];
    const float* Wr_f     = (const float*)d_in[4];
    const float* b_f      = (const float*)d_in[5];
    const float* Wk_b     = (const float*)d_in[6];
    const float* Wr_b     = (const float*)d_in[7];
    const float* b_b      = (const float*)d_in[8];
    const float* W1       = (const float*)d_in[9];
    const float* b1       = (const float*)d_in[10];
    const float* W2       = (const float*)d_in[11];
    const float* b2       = (const float*)d_in[12];
    const float* We       = (const float*)d_in[13];
    const float* be       = (const float*)d_in[14];
    const float* Ws       = (const float*)d_in[15];
    const float* bs       = (const float*)d_in[16];
    float* out = (float*)d_out;

    zeroH_kernel<<<1, 320>>>();
    embZ_kernel<<<dim3(SEQ / TE, 2), 160>>>(sentence, E, Wk_f, b_f, Wk_b, b_b);
    lstm_rec_kernel<<<dim3(NCTA, 2), 160>>>(Wr_f, Wr_b);
    outGemm_kernel<<<SEQ / TT, 320>>>(W1, b1);
    syn_kernel<<<SEQ, 128>>>(sentence, syn, E, W2, b2);
    heads_kernel<<<1, 32>>>(We, be, Ws, bs, out);
}